// round 2
// baseline (speedup 1.0000x reference)
#include <cuda_runtime.h>
#include <math.h>

#define LSEQ 2048
#define DIM  256
#define BATCH 8

// Scratch (static device globals — no runtime allocation allowed)
static __device__ float g_scores[(size_t)BATCH * LSEQ * LSEQ];   // 134 MB, reused as alpha
static __device__ float g_aug[(size_t)BATCH * LSEQ * DIM];       // 16 MB
static __device__ float g_gate[BATCH * LSEQ];

#define BM 64
#define BN 64
#define BK 16

// ---------------------------------------------------------------------------
// Kernel 1: scores[b,i,j] = dot(c2[b,i,:], c1[b,j,:]) with diag + key masking
// ---------------------------------------------------------------------------
__global__ __launch_bounds__(256) void k_scores(const float* __restrict__ c1,
                                                const float* __restrict__ c2,
                                                const unsigned char* __restrict__ cmask) {
    __shared__ float sA[BK][BM + 1];
    __shared__ float sB[BK][BN + 1];
    const int b  = blockIdx.z;
    const int i0 = blockIdx.y * BM;
    const int j0 = blockIdx.x * BN;
    const float* A  = c2 + (size_t)b * LSEQ * DIM;
    const float* Bp = c1 + (size_t)b * LSEQ * DIM;

    const int tid = threadIdx.x;
    const int lk = tid & 15, lm = tid >> 4;   // load mapping
    const int tx = tid & 15, ty = tid >> 4;   // compute mapping

    float acc[4][4];
#pragma unroll
    for (int r = 0; r < 4; r++)
#pragma unroll
        for (int c = 0; c < 4; c++) acc[r][c] = 0.f;

    for (int kt = 0; kt < DIM; kt += BK) {
#pragma unroll
        for (int r = 0; r < 4; r++) {
            sA[lk][lm + 16 * r] = A[(size_t)(i0 + lm + 16 * r) * DIM + kt + lk];
            sB[lk][lm + 16 * r] = Bp[(size_t)(j0 + lm + 16 * r) * DIM + kt + lk];
        }
        __syncthreads();
#pragma unroll
        for (int k = 0; k < BK; k++) {
            float a[4], bb[4];
#pragma unroll
            for (int r = 0; r < 4; r++) a[r] = sA[k][ty + 16 * r];
#pragma unroll
            for (int c = 0; c < 4; c++) bb[c] = sB[k][tx + 16 * c];
#pragma unroll
            for (int r = 0; r < 4; r++)
#pragma unroll
                for (int c = 0; c < 4; c++) acc[r][c] = fmaf(a[r], bb[c], acc[r][c]);
        }
        __syncthreads();
    }

#pragma unroll
    for (int r = 0; r < 4; r++) {
        const int gi = i0 + ty + 16 * r;
#pragma unroll
        for (int c = 0; c < 4; c++) {
            const int gj = j0 + tx + 16 * c;
            float v = acc[r][c];
            if (gi == gj || cmask[b * LSEQ + gj]) v = -INFINITY;
            g_scores[((size_t)b * LSEQ + gi) * LSEQ + gj] = v;
        }
    }
}

// ---------------------------------------------------------------------------
// Kernel 2: in-place row softmax over j (row length 2048), one block per row
// ---------------------------------------------------------------------------
__global__ __launch_bounds__(256) void k_softmax() {
    const int row = blockIdx.x;
    float* p = g_scores + (size_t)row * LSEQ;
    const int t = threadIdx.x;

    float v[8];
    float m = -INFINITY;
#pragma unroll
    for (int r = 0; r < 8; r++) {
        v[r] = p[t + 256 * r];
        m = fmaxf(m, v[r]);
    }
    __shared__ float red[256];
    red[t] = m;
    __syncthreads();
    for (int s = 128; s > 0; s >>= 1) {
        if (t < s) red[t] = fmaxf(red[t], red[t + s]);
        __syncthreads();
    }
    m = red[0];
    __syncthreads();

    float sum = 0.f;
#pragma unroll
    for (int r = 0; r < 8; r++) {
        v[r] = __expf(v[r] - m);   // exp(-inf - m) == 0
        sum += v[r];
    }
    red[t] = sum;
    __syncthreads();
    for (int s = 128; s > 0; s >>= 1) {
        if (t < s) red[t] += red[t + s];
        __syncthreads();
    }
    const float inv = 1.f / red[0];
#pragma unroll
    for (int r = 0; r < 8; r++) p[t + 256 * r] = v[r] * inv;
}

// ---------------------------------------------------------------------------
// Kernel 3: aug[b,i,d] = sum_j alpha[b,i,j] * c1[b,j,d]
// ---------------------------------------------------------------------------
__global__ __launch_bounds__(256) void k_aug(const float* __restrict__ c1) {
    __shared__ float sA[BK][BM + 1];
    __shared__ float sB[BK][BN + 1];
    const int b  = blockIdx.z;
    const int i0 = blockIdx.y * BM;
    const int n0 = blockIdx.x * BN;
    const float* A  = g_scores + (size_t)b * LSEQ * LSEQ;
    const float* Bp = c1 + (size_t)b * LSEQ * DIM;

    const int tid = threadIdx.x;
    const int lk = tid & 15, lm = tid >> 4;
    const int ln = tid & 63, lkb = tid >> 6;
    const int tx = tid & 15, ty = tid >> 4;

    float acc[4][4];
#pragma unroll
    for (int r = 0; r < 4; r++)
#pragma unroll
        for (int c = 0; c < 4; c++) acc[r][c] = 0.f;

    for (int kt = 0; kt < LSEQ; kt += BK) {
#pragma unroll
        for (int r = 0; r < 4; r++)
            sA[lk][lm + 16 * r] = A[(size_t)(i0 + lm + 16 * r) * LSEQ + kt + lk];
#pragma unroll
        for (int r = 0; r < 4; r++)
            sB[lkb + 4 * r][ln] = Bp[(size_t)(kt + lkb + 4 * r) * DIM + n0 + ln];
        __syncthreads();
#pragma unroll
        for (int k = 0; k < BK; k++) {
            float a[4], bb[4];
#pragma unroll
            for (int r = 0; r < 4; r++) a[r] = sA[k][ty + 16 * r];
#pragma unroll
            for (int c = 0; c < 4; c++) bb[c] = sB[k][tx + 16 * c];
#pragma unroll
            for (int r = 0; r < 4; r++)
#pragma unroll
                for (int c = 0; c < 4; c++) acc[r][c] = fmaf(a[r], bb[c], acc[r][c]);
        }
        __syncthreads();
    }

#pragma unroll
    for (int r = 0; r < 4; r++) {
        const int gi = i0 + ty + 16 * r;
#pragma unroll
        for (int c = 0; c < 4; c++) {
            const int gn = n0 + tx + 16 * c;
            g_aug[((size_t)b * LSEQ + gi) * DIM + gn] = acc[r][c];
        }
    }
}

// ---------------------------------------------------------------------------
// Kernel 4: gate[row] = sigmoid(z . W_g + b_g), one block per row
// ---------------------------------------------------------------------------
__global__ __launch_bounds__(256) void k_gate(const float* __restrict__ c2,
                                              const float* __restrict__ Wg,
                                              const float* __restrict__ bg) {
    const int row = blockIdx.x;
    const int t = threadIdx.x;
    const float c2v = c2[(size_t)row * DIM + t];
    const float av  = g_aug[(size_t)row * DIM + t];
    float part = c2v * Wg[t] + av * Wg[DIM + t] + (c2v * av) * Wg[2 * DIM + t] +
                 (c2v - av) * Wg[3 * DIM + t];
    __shared__ float red[256];
    red[t] = part;
    __syncthreads();
    for (int s = 128; s > 0; s >>= 1) {
        if (t < s) red[t] += red[t + s];
        __syncthreads();
    }
    if (t == 0) {
        const float x = red[0] + bg[0];
        g_gate[row] = 1.f / (1.f + __expf(-x));
    }
}

// ---------------------------------------------------------------------------
// Kernel 5: fusion GEMM  Z[16384,1024] @ W_f[1024,256] with fused epilogue
//   Z formed on the fly: seg 0: c2, 1: aug, 2: c2*aug, 3: c2-aug
//   out = g*tanh(acc + b_f) + (1-g)*c2
// ---------------------------------------------------------------------------
__global__ __launch_bounds__(256) void k_fusion(const float* __restrict__ c2,
                                                const float* __restrict__ Wf,
                                                const float* __restrict__ bf,
                                                float* __restrict__ out) {
    __shared__ float sA[BK][BM + 1];
    __shared__ float sB[BK][BN + 1];
    const int m0 = blockIdx.y * BM;   // global row block (over B*L = 16384)
    const int n0 = blockIdx.x * BN;   // output-dim block (over 256)

    const int tid = threadIdx.x;
    const int lk = tid & 15, lm = tid >> 4;
    const int ln = tid & 63, lkb = tid >> 6;
    const int tx = tid & 15, ty = tid >> 4;

    float acc[4][4];
#pragma unroll
    for (int r = 0; r < 4; r++)
#pragma unroll
        for (int c = 0; c < 4; c++) acc[r][c] = 0.f;

    for (int kt = 0; kt < 4 * DIM; kt += BK) {
        const int seg = kt >> 8;           // BK=16 divides 256 -> segment constant per tile
        const int d0  = kt & 255;
#pragma unroll
        for (int r = 0; r < 4; r++) {
            const int row = m0 + lm + 16 * r;
            const int d = d0 + lk;
            const float c2v = c2[(size_t)row * DIM + d];
            const float av  = g_aug[(size_t)row * DIM + d];
            float zv;
            if (seg == 0)      zv = c2v;
            else if (seg == 1) zv = av;
            else if (seg == 2) zv = c2v * av;
            else               zv = c2v - av;
            sA[lk][lm + 16 * r] = zv;
        }
#pragma unroll
        for (int r = 0; r < 4; r++)
            sB[lkb + 4 * r][ln] = Wf[(size_t)(kt + lkb + 4 * r) * DIM + n0 + ln];
        __syncthreads();
#pragma unroll
        for (int k = 0; k < BK; k++) {
            float a[4], bb[4];
#pragma unroll
            for (int r = 0; r < 4; r++) a[r] = sA[k][ty + 16 * r];
#pragma unroll
            for (int c = 0; c < 4; c++) bb[c] = sB[k][tx + 16 * c];
#pragma unroll
            for (int r = 0; r < 4; r++)
#pragma unroll
                for (int c = 0; c < 4; c++) acc[r][c] = fmaf(a[r], bb[c], acc[r][c]);
        }
        __syncthreads();
    }

#pragma unroll
    for (int r = 0; r < 4; r++) {
        const int grow = m0 + ty + 16 * r;
        const float g = g_gate[grow];
#pragma unroll
        for (int c = 0; c < 4; c++) {
            const int col = n0 + tx + 16 * c;
            const float f = tanhf(acc[r][c] + bf[col]);
            const float c2v = c2[(size_t)grow * DIM + col];
            out[(size_t)grow * DIM + col] = g * f + (1.f - g) * c2v;
        }
    }
}

// ---------------------------------------------------------------------------
extern "C" void kernel_launch(void* const* d_in, const int* in_sizes, int n_in,
                              void* d_out, int out_size) {
    const float* c1 = (const float*)d_in[0];
    const float* c2 = (const float*)d_in[1];
    const unsigned char* cmask = (const unsigned char*)d_in[2];
    const float* Wf = (const float*)d_in[3];
    const float* bf = (const float*)d_in[4];
    const float* Wg = (const float*)d_in[5];
    const float* bg = (const float*)d_in[6];
    float* out = (float*)d_out;

    dim3 blk(256);
    k_scores<<<dim3(LSEQ / BN, LSEQ / BM, BATCH), blk>>>(c1, c2, cmask);
    k_softmax<<<dim3(BATCH * LSEQ), blk>>>();
    k_aug<<<dim3(DIM / BN, LSEQ / BM, BATCH), blk>>>(c1);
    k_gate<<<dim3(BATCH * LSEQ), blk>>>(c2, Wg, bg);
    k_fusion<<<dim3(DIM / BN, (BATCH * LSEQ) / BM), blk>>>(c2, Wf, bf, out);
}

// round 5
// speedup vs baseline: 2.9553x; 2.9553x over previous
#include <cuda_runtime.h>
#include <cuda_bf16.h>
#include <cstdint>
#include <math.h>

#define LSEQ 2048
#define DIM  256
#define BATCH 8

#define KC 32          // bf16 k per chunk
#define PAD_STR 40     // smem row stride in elements (80B: conflict-free for ldmatrix)
#define TILE_B (128 * PAD_STR * 2)          // 10240 bytes per tile
#define STAGE_B (4 * TILE_B)                // Ah, Al, Bh, Bl
#define SMEM_DYN (2 * STAGE_B)              // 2 stages = 81920 bytes

// ============================ PTX helpers ====================================
__device__ __forceinline__ uint32_t smem_to_u32(const void* p) {
    uint32_t a;
    asm("{ .reg .u64 t; cvta.to.shared.u64 t, %1; cvt.u32.u64 %0, t; }"
        : "=r"(a) : "l"(p));
    return a;
}
__device__ __forceinline__ void cp_async16(uint32_t dst, const void* src) {
    asm volatile("cp.async.cg.shared.global [%0], [%1], 16;" :: "r"(dst), "l"(src));
}
#define CP_COMMIT() asm volatile("cp.async.commit_group;" ::: "memory")
#define CP_WAIT0()  asm volatile("cp.async.wait_group 0;" ::: "memory")
#define CP_WAIT1()  asm volatile("cp.async.wait_group 1;" ::: "memory")

__device__ __forceinline__ void ldsm_x4(uint32_t addr, uint32_t* r) {
    asm volatile("ldmatrix.sync.aligned.m8n8.x4.shared.b16 {%0,%1,%2,%3}, [%4];"
                 : "=r"(r[0]), "=r"(r[1]), "=r"(r[2]), "=r"(r[3]) : "r"(addr));
}
__device__ __forceinline__ void mma_bf16(float* c, const uint32_t* a, const uint32_t* b) {
    asm volatile(
        "mma.sync.aligned.m16n8k16.row.col.f32.bf16.bf16.f32 "
        "{%0,%1,%2,%3}, {%4,%5,%6,%7}, {%8,%9}, {%0,%1,%2,%3};"
        : "+f"(c[0]), "+f"(c[1]), "+f"(c[2]), "+f"(c[3])
        : "r"(a[0]), "r"(a[1]), "r"(a[2]), "r"(a[3]), "r"(b[0]), "r"(b[1]));
}

// ============================ device scratch =================================
static __device__ __nv_bfloat16 g_c1_hi[(size_t)BATCH * LSEQ * DIM];
static __device__ __nv_bfloat16 g_c1_lo[(size_t)BATCH * LSEQ * DIM];
static __device__ __nv_bfloat16 g_c2_hi[(size_t)BATCH * LSEQ * DIM];
static __device__ __nv_bfloat16 g_c2_lo[(size_t)BATCH * LSEQ * DIM];
static __device__ __nv_bfloat16 g_c1t_hi[(size_t)BATCH * DIM * LSEQ];
static __device__ __nv_bfloat16 g_c1t_lo[(size_t)BATCH * DIM * LSEQ];
static __device__ __nv_bfloat16 g_wft_hi[(size_t)DIM * 4 * DIM];   // [n=256][k=1024]
static __device__ __nv_bfloat16 g_wft_lo[(size_t)DIM * 4 * DIM];
static __device__ float         g_scores[(size_t)BATCH * LSEQ * LSEQ];
static __device__ __nv_bfloat16 g_alpha_hi[(size_t)BATCH * LSEQ * LSEQ];
static __device__ __nv_bfloat16 g_alpha_lo[(size_t)BATCH * LSEQ * LSEQ];
static __device__ float         g_aug[(size_t)BATCH * LSEQ * DIM];
static __device__ __nv_bfloat16 g_z_hi[(size_t)BATCH * LSEQ * 4 * DIM];
static __device__ __nv_bfloat16 g_z_lo[(size_t)BATCH * LSEQ * 4 * DIM];
static __device__ float         g_gate[BATCH * LSEQ];

// ============================ prep kernels ===================================
__global__ __launch_bounds__(256) void k_prep_split(const float* __restrict__ c1,
                                                    const float* __restrict__ c2) {
    size_t i = (size_t)blockIdx.x * 256 + threadIdx.x;
    if (i < (size_t)BATCH * LSEQ * DIM) {
        float v = c1[i];
        __nv_bfloat16 h = __float2bfloat16(v);
        g_c1_hi[i] = h;
        g_c1_lo[i] = __float2bfloat16(v - __bfloat162float(h));
        v = c2[i];
        h = __float2bfloat16(v);
        g_c2_hi[i] = h;
        g_c2_lo[i] = __float2bfloat16(v - __bfloat162float(h));
    }
}

__global__ __launch_bounds__(256) void k_prep_t(const float* __restrict__ c1) {
    __shared__ float tile[32][33];
    const int b = blockIdx.z;
    const int j0 = blockIdx.x * 32, d0 = blockIdx.y * 32;
    const float* src = c1 + (size_t)b * LSEQ * DIM;
    const int tx = threadIdx.x, ty = threadIdx.y;  // block (32, 8)
#pragma unroll
    for (int r = 0; r < 32; r += 8)
        tile[ty + r][tx] = src[(size_t)(j0 + ty + r) * DIM + d0 + tx];
    __syncthreads();
#pragma unroll
    for (int r = 0; r < 32; r += 8) {
        float v = tile[tx][ty + r];
        __nv_bfloat16 h = __float2bfloat16(v);
        size_t o = (size_t)b * DIM * LSEQ + (size_t)(d0 + ty + r) * LSEQ + j0 + tx;
        g_c1t_hi[o] = h;
        g_c1t_lo[o] = __float2bfloat16(v - __bfloat162float(h));
    }
}

__global__ __launch_bounds__(256) void k_prep_wft(const float* __restrict__ Wf) {
    int i = blockIdx.x * 256 + threadIdx.x;  // i = n*1024 + k
    if (i < DIM * 4 * DIM) {
        int n = i >> 10, k = i & 1023;
        float v = Wf[(size_t)k * DIM + n];
        __nv_bfloat16 h = __float2bfloat16(v);
        g_wft_hi[i] = h;
        g_wft_lo[i] = __float2bfloat16(v - __bfloat162float(h));
    }
}

// ============================ GEMM mainloop ==================================
// Block tile 128x128, 8 warps, warp tile 64x32 (warp grid 2m x 4n).
// A: [m][k] row-major hi/lo; B: [n][k] row-major hi/lo (i.e. B^T).
// 3 passes: Ah*Bh + Ah*Bl + Al*Bh accumulated into fp32.
__device__ __forceinline__ void load_chunk(uint32_t sbase,
                                           const __nv_bfloat16* __restrict__ Ah,
                                           const __nv_bfloat16* __restrict__ Al,
                                           size_t aStr,
                                           const __nv_bfloat16* __restrict__ Bh,
                                           const __nv_bfloat16* __restrict__ Bl,
                                           size_t bStr, int kOff) {
    const int t = threadIdx.x;
    const int c = (t & 3) * 8;   // bf16 col within 32
    const int r = t >> 2;        // 0..63
    const uint32_t soff = (uint32_t)(r * PAD_STR + c) * 2;
    const uint32_t soff2 = soff + 64 * PAD_STR * 2;
    {
        const __nv_bfloat16* g = Ah + (size_t)r * aStr + kOff + c;
        cp_async16(sbase + 0 * TILE_B + soff, g);
        cp_async16(sbase + 0 * TILE_B + soff2, g + 64 * aStr);
    }
    {
        const __nv_bfloat16* g = Al + (size_t)r * aStr + kOff + c;
        cp_async16(sbase + 1 * TILE_B + soff, g);
        cp_async16(sbase + 1 * TILE_B + soff2, g + 64 * aStr);
    }
    {
        const __nv_bfloat16* g = Bh + (size_t)r * bStr + kOff + c;
        cp_async16(sbase + 2 * TILE_B + soff, g);
        cp_async16(sbase + 2 * TILE_B + soff2, g + 64 * bStr);
    }
    {
        const __nv_bfloat16* g = Bl + (size_t)r * bStr + kOff + c;
        cp_async16(sbase + 3 * TILE_B + soff, g);
        cp_async16(sbase + 3 * TILE_B + soff2, g + 64 * bStr);
    }
}

__device__ __forceinline__ void gemm_tile(const __nv_bfloat16* __restrict__ Ah,
                                          const __nv_bfloat16* __restrict__ Al,
                                          size_t aStr,
                                          const __nv_bfloat16* __restrict__ Bh,
                                          const __nv_bfloat16* __restrict__ Bl,
                                          size_t bStr, int nChunks, char* sm,
                                          float acc[4][4][4]) {
    const int t = threadIdx.x;
    const int w = t >> 5, lane = t & 31;
    const int wm = (w & 1) * 64;        // warp m offset
    const int wn = (w >> 1) * 32;       // warp n offset
    const uint32_t smb = smem_to_u32(sm);

#pragma unroll
    for (int mf = 0; mf < 4; mf++)
#pragma unroll
        for (int nf = 0; nf < 4; nf++)
#pragma unroll
            for (int e = 0; e < 4; e++) acc[mf][nf][e] = 0.f;

    // per-lane ldmatrix base offsets
    const int arow = wm + (lane & 15);
    const int acol = (lane >> 4) * 8;
    const int brow = wn + (lane & 7) + ((lane >> 4) ? 8 : 0);
    const int bcol = ((lane >> 3) & 1) * 8;

    load_chunk(smb, Ah, Al, aStr, Bh, Bl, bStr, 0);
    CP_COMMIT();

    for (int kc = 0; kc < nChunks; kc++) {
        const uint32_t s = (uint32_t)(kc & 1) * STAGE_B;
        if (kc + 1 < nChunks) {
            load_chunk(smb + (STAGE_B - s), Ah, Al, aStr, Bh, Bl, bStr, (kc + 1) * KC);
            CP_COMMIT();
            CP_WAIT1();
        } else {
            CP_WAIT0();
        }
        __syncthreads();

        const uint32_t sah = smb + s + 0 * TILE_B;
        const uint32_t sal = smb + s + 1 * TILE_B;
        const uint32_t sbh = smb + s + 2 * TILE_B;
        const uint32_t sbl = smb + s + 3 * TILE_B;

#pragma unroll
        for (int ks = 0; ks < 2; ks++) {
            const int k0 = ks * 16;
            uint32_t ah[4][4], al[4][4], bh[2][4], bl[2][4];
#pragma unroll
            for (int mf = 0; mf < 4; mf++) {
                const uint32_t off = (uint32_t)((arow + mf * 16) * PAD_STR + acol + k0) * 2;
                ldsm_x4(sah + off, ah[mf]);
                ldsm_x4(sal + off, al[mf]);
            }
#pragma unroll
            for (int nb = 0; nb < 2; nb++) {
                const uint32_t off = (uint32_t)((brow + nb * 16) * PAD_STR + bcol + k0) * 2;
                ldsm_x4(sbh + off, bh[nb]);
                ldsm_x4(sbl + off, bl[nb]);
            }
#pragma unroll
            for (int mf = 0; mf < 4; mf++)
#pragma unroll
                for (int nf = 0; nf < 4; nf++) {
                    const uint32_t* bhp = &bh[nf >> 1][(nf & 1) * 2];
                    const uint32_t* blp = &bl[nf >> 1][(nf & 1) * 2];
                    mma_bf16(acc[mf][nf], ah[mf], bhp);
                    mma_bf16(acc[mf][nf], ah[mf], blp);
                    mma_bf16(acc[mf][nf], al[mf], bhp);
                }
        }
        __syncthreads();
    }
}

// ============================ GEMM kernels ===================================
__global__ __launch_bounds__(256, 1) void k_gemm_scores(const unsigned char* __restrict__ cmask) {
    extern __shared__ char sm[];
    const int b = blockIdx.z, i0 = blockIdx.y * 128, j0 = blockIdx.x * 128;
    const size_t aBase = ((size_t)b * LSEQ + i0) * DIM;
    const size_t bBase = ((size_t)b * LSEQ + j0) * DIM;
    float acc[4][4][4];
    gemm_tile(g_c2_hi + aBase, g_c2_lo + aBase, DIM,
              g_c1_hi + bBase, g_c1_lo + bBase, DIM, DIM / KC, sm, acc);

    const int w = threadIdx.x >> 5, lane = threadIdx.x & 31;
    const int wm = (w & 1) * 64, wn = (w >> 1) * 32;
#pragma unroll
    for (int mf = 0; mf < 4; mf++)
#pragma unroll
        for (int nf = 0; nf < 4; nf++) {
            const int gj = j0 + wn + nf * 8 + (lane & 3) * 2;
            const unsigned char m0 = cmask[b * LSEQ + gj];
            const unsigned char m1 = cmask[b * LSEQ + gj + 1];
#pragma unroll
            for (int half = 0; half < 2; half++) {
                const int gi = i0 + wm + mf * 16 + (lane >> 2) + half * 8;
                float2 v = make_float2(acc[mf][nf][2 * half], acc[mf][nf][2 * half + 1]);
                if (gi == gj || m0) v.x = -INFINITY;
                if (gi == gj + 1 || m1) v.y = -INFINITY;
                *(float2*)&g_scores[((size_t)(b * LSEQ) + gi) * LSEQ + gj] = v;
            }
        }
}

__global__ __launch_bounds__(256, 1) void k_gemm_aug() {
    extern __shared__ char sm[];
    const int b = blockIdx.z, i0 = blockIdx.y * 128, n0 = blockIdx.x * 128;
    const size_t aBase = ((size_t)b * LSEQ + i0) * LSEQ;
    const size_t bBase = ((size_t)b * DIM + n0) * LSEQ;
    float acc[4][4][4];
    gemm_tile(g_alpha_hi + aBase, g_alpha_lo + aBase, LSEQ,
              g_c1t_hi + bBase, g_c1t_lo + bBase, LSEQ, LSEQ / KC, sm, acc);

    const int w = threadIdx.x >> 5, lane = threadIdx.x & 31;
    const int wm = (w & 1) * 64, wn = (w >> 1) * 32;
#pragma unroll
    for (int mf = 0; mf < 4; mf++)
#pragma unroll
        for (int nf = 0; nf < 4; nf++) {
            const int gn = n0 + wn + nf * 8 + (lane & 3) * 2;
#pragma unroll
            for (int half = 0; half < 2; half++) {
                const int gi = i0 + wm + mf * 16 + (lane >> 2) + half * 8;
                float2 v = make_float2(acc[mf][nf][2 * half], acc[mf][nf][2 * half + 1]);
                *(float2*)&g_aug[((size_t)(b * LSEQ) + gi) * DIM + gn] = v;
            }
        }
}

__global__ __launch_bounds__(256, 1) void k_gemm_fusion(const float* __restrict__ c2,
                                                        const float* __restrict__ bf,
                                                        float* __restrict__ out) {
    extern __shared__ char sm[];
    const int n0 = blockIdx.x * 128, m0 = blockIdx.y * 128;
    const size_t aBase = (size_t)m0 * (4 * DIM);
    const size_t bBase = (size_t)n0 * (4 * DIM);
    float acc[4][4][4];
    gemm_tile(g_z_hi + aBase, g_z_lo + aBase, 4 * DIM,
              g_wft_hi + bBase, g_wft_lo + bBase, 4 * DIM, (4 * DIM) / KC, sm, acc);

    const int w = threadIdx.x >> 5, lane = threadIdx.x & 31;
    const int wm = (w & 1) * 64, wn = (w >> 1) * 32;
#pragma unroll
    for (int mf = 0; mf < 4; mf++)
#pragma unroll
        for (int nf = 0; nf < 4; nf++) {
            const int col = n0 + wn + nf * 8 + (lane & 3) * 2;
            const float bf0 = bf[col], bf1 = bf[col + 1];
#pragma unroll
            for (int half = 0; half < 2; half++) {
                const int grow = m0 + wm + mf * 16 + (lane >> 2) + half * 8;
                const float g = g_gate[grow];
                const float2 cv = *(const float2*)&c2[(size_t)grow * DIM + col];
                float2 v;
                v.x = g * tanhf(acc[mf][nf][2 * half] + bf0) + (1.f - g) * cv.x;
                v.y = g * tanhf(acc[mf][nf][2 * half + 1] + bf1) + (1.f - g) * cv.y;
                *(float2*)&out[(size_t)grow * DIM + col] = v;
            }
        }
}

// ============================ softmax + alpha split ==========================
__global__ __launch_bounds__(256) void k_softmax() {
    const size_t row = blockIdx.x;
    const float* p = g_scores + row * LSEQ;
    const int t = threadIdx.x;

    float v[8];
    float m = -INFINITY;
#pragma unroll
    for (int r = 0; r < 8; r++) {
        v[r] = p[t + 256 * r];
        m = fmaxf(m, v[r]);
    }
    __shared__ float red[256];
    red[t] = m;
    __syncthreads();
    for (int s = 128; s > 0; s >>= 1) {
        if (t < s) red[t] = fmaxf(red[t], red[t + s]);
        __syncthreads();
    }
    m = red[0];
    __syncthreads();

    float sum = 0.f;
#pragma unroll
    for (int r = 0; r < 8; r++) {
        v[r] = __expf(v[r] - m);
        sum += v[r];
    }
    red[t] = sum;
    __syncthreads();
    for (int s = 128; s > 0; s >>= 1) {
        if (t < s) red[t] += red[t + s];
        __syncthreads();
    }
    const float inv = 1.f / red[0];
#pragma unroll
    for (int r = 0; r < 8; r++) {
        const float a = v[r] * inv;
        const __nv_bfloat16 h = __float2bfloat16(a);
        const size_t o = row * LSEQ + t + 256 * r;
        g_alpha_hi[o] = h;
        g_alpha_lo[o] = __float2bfloat16(a - __bfloat162float(h));
    }
}

// ============================ z prep + gate ==================================
__global__ __launch_bounds__(256) void k_prep_z(const float* __restrict__ c2,
                                                const float* __restrict__ Wg,
                                                const float* __restrict__ bg) {
    const int m = blockIdx.x;
    const int t = threadIdx.x;
    const float c2v = c2[(size_t)m * DIM + t];
    const float av  = g_aug[(size_t)m * DIM + t];
    const float z[4] = {c2v, av, c2v * av, c2v - av};
    float part = 0.f;
#pragma unroll
    for (int s = 0; s < 4; s++) {
        const size_t o = (size_t)m * (4 * DIM) + s * DIM + t;
        const __nv_bfloat16 h = __float2bfloat16(z[s]);
        g_z_hi[o] = h;
        g_z_lo[o] = __float2bfloat16(z[s] - __bfloat162float(h));
        part += z[s] * Wg[s * DIM + t];
    }
    __shared__ float red[256];
    red[t] = part;
    __syncthreads();
    for (int s = 128; s > 0; s >>= 1) {
        if (t < s) red[t] += red[t + s];
        __syncthreads();
    }
    if (t == 0) g_gate[m] = 1.f / (1.f + __expf(-(red[0] + bg[0])));
}

// ============================ launch =========================================
extern "C" void kernel_launch(void* const* d_in, const int* in_sizes, int n_in,
                              void* d_out, int out_size) {
    const float* c1 = (const float*)d_in[0];
    const float* c2 = (const float*)d_in[1];
    const unsigned char* cmask = (const unsigned char*)d_in[2];
    const float* Wf = (const float*)d_in[3];
    const float* bf = (const float*)d_in[4];
    const float* Wg = (const float*)d_in[5];
    const float* bg = (const float*)d_in[6];
    float* out = (float*)d_out;

    cudaFuncSetAttribute(k_gemm_scores, cudaFuncAttributeMaxDynamicSharedMemorySize, SMEM_DYN);
    cudaFuncSetAttribute(k_gemm_aug,    cudaFuncAttributeMaxDynamicSharedMemorySize, SMEM_DYN);
    cudaFuncSetAttribute(k_gemm_fusion, cudaFuncAttributeMaxDynamicSharedMemorySize, SMEM_DYN);

    k_prep_split<<<(BATCH * LSEQ * DIM) / 256, 256>>>(c1, c2);
    k_prep_t<<<dim3(LSEQ / 32, DIM / 32, BATCH), dim3(32, 8)>>>(c1);
    k_prep_wft<<<(DIM * 4 * DIM) / 256, 256>>>(Wf);

    k_gemm_scores<<<dim3(LSEQ / 128, LSEQ / 128, BATCH), 256, SMEM_DYN>>>(cmask);
    k_softmax<<<BATCH * LSEQ, 256>>>();
    k_gemm_aug<<<dim3(DIM / 128, LSEQ / 128, BATCH), 256, SMEM_DYN>>>();
    k_prep_z<<<BATCH * LSEQ, 256>>>(c2, Wg, bg);
    k_gemm_fusion<<<dim3(DIM / 128, (BATCH * LSEQ) / 128), 256, SMEM_DYN>>>(c2, bf, out);
}